// round 8
// baseline (speedup 1.0000x reference)
#include <cuda_runtime.h>
#include <cuda_bf16.h>
#include <math.h>

#define ATOMS_N 48
#define NSPEC 4
#define RAD_LEN 64
#define ANG_SUB 32
#define ANG_LEN 320
#define AEV_LEN 384
#define RCR_F 5.2f
#define RCA_F 3.5f
#define PI_F 3.14159265358979323846f
#define SQRT095_F 0.974679434f   /* sqrt(0.95) */
#define SQRT2_F   1.414213562f

__global__ __launch_bounds__(128, 11)
void aev_kernel(const float* __restrict__ coords,
                const float* __restrict__ EtaR,
                const float* __restrict__ ShfR,
                const float* __restrict__ EtaA,
                const float* __restrict__ Zeta,
                const float* __restrict__ ShfA,
                const float* __restrict__ ShfZ,
                const int*   __restrict__ species,
                float* __restrict__ out)
{
    __shared__ float sc[ATOMS_N * 3];
    __shared__ float dd[ATOMS_N], fcR[ATOMS_N];
    __shared__ int   ssp[ATOMS_N];
    // compacted angular-neighbor arrays
    __shared__ float adx[ATOMS_N], ady[ATOMS_N], adz[ATOMS_N];
    __shared__ float adh[ATOMS_N], ainv[ATOMS_N], afcs[ATOMS_N];
    __shared__ int   asp[ATOMS_N];
    __shared__ int   ncnt;
    __shared__ float acc[AEV_LEN];
    __shared__ float shR[16], shA[4], czv[8], szv[8];
    __shared__ float sP[3]; // etaR, etaA, zeta

    const int tid = threadIdx.x;
    const int m  = blockIdx.x / ATOMS_N;
    const int ci = blockIdx.x % ATOMS_N;

    // ---- coalesced loads + params + zero accumulator ----
    sc[tid] = coords[m * 144 + tid];
    if (tid < 16) sc[128 + tid] = coords[m * 144 + 128 + tid];
    int myspec = 0;
    if (tid < ATOMS_N) {
        myspec = species[m * ATOMS_N + tid];
        ssp[tid] = myspec;
    }
    if (tid >= 64 && tid < 80) shR[tid - 64] = ShfR[tid - 64];
    if (tid >= 80 && tid < 84) shA[tid - 80] = ShfA[tid - 80];
    if (tid >= 88 && tid < 96) {
        float v = ShfZ[tid - 88];
        czv[tid - 88] = cosf(v);
        szv[tid - 88] = sinf(v);
    }
    if (tid == 96) sP[0] = EtaR[0];
    if (tid == 97) sP[1] = EtaA[0];
    if (tid == 98) sP[2] = Zeta[0];
    if (tid == 99) ncnt = 0;
    acc[tid] = 0.0f; acc[tid + 128] = 0.0f; acc[tid + 256] = 0.0f;
    __syncthreads();

    // ---- parallel geometry: one atom per thread (48 threads) + atomic compaction ----
    if (tid < ATOMS_N) {
        const float cx = sc[3 * ci], cy = sc[3 * ci + 1], cz = sc[3 * ci + 2];
        float dx = sc[3 * tid]     - cx;
        float dy = sc[3 * tid + 1] - cy;
        float dz = sc[3 * tid + 2] - cz;
        float d  = sqrtf(dx * dx + dy * dy + dz * dz);
        dd[tid]  = d;
        fcR[tid] = 0.5f * __cosf(d * (PI_F / RCR_F)) + 0.5f;

        if ((tid != ci) & (d <= RCA_F)) {
            float fa = 0.5f * __cosf(d * (PI_F / RCA_F)) + 0.5f;
            int p = atomicAdd(&ncnt, 1);
            adx[p] = dx; ady[p] = dy; adz[p] = dz;
            adh[p] = 0.5f * d;
            ainv[p] = SQRT095_F * __frcp_rn(fmaxf(d, 1e-8f));
            afcs[p] = SQRT2_F * fa;
            asp[p] = myspec;
        }
    }
    __syncthreads();

    // ---- radial: atom-centric, 768 work items, 6 per thread, fixed r ----
    // Writes acc[0..64); angular writes acc[64..384) — disjoint, no barrier.
    {
        const int r  = tid & 15;
        const int j0 = tid >> 4;
        const float er = sP[0];
        const float sh = shR[r];
        #pragma unroll
        for (int i = 0; i < 6; i++) {
            int j = j0 + (i << 3);
            float d = dd[j];
            float t = d - sh;
            float e = 0.25f * __expf(-er * t * t) * fcR[j];
            if ((j != ci) & (d <= RCR_F))
                atomicAdd(&acc[(ssp[j] << 4) + r], e);
        }
    }

    // ---- angular: 2 threads per pair (z-halves), conflict-free banks ----
    {
        const int lane = tid & 31;
        const int zh   = (lane & 1) << 2;   // z-half base: 0 or 4
        const int zo   = (lane >> 1) & 3;   // z rotation within half
        const int ar   = (lane >> 3) & 3;   // a rotation

        const float etaA = sP[1];
        const float zeta = sP[2];
        const bool  z32  = (zeta == 32.0f);

        const int n     = ncnt;
        const int npair = (n * (n - 1)) >> 1;
        const float fn  = (float)(2 * n - 1);

        for (int q = (tid >> 1); q < npair; q += 64) {
            // closed-form upper-triangular decode with one-step fixup
            float disc = fn * fn - 8.0f * (float)q;
            int jj = (int)(0.5f * (fn - sqrtf(disc)));
            int off = (jj * (2 * n - 1 - jj)) >> 1;
            if (off > q) { jj--; off = (jj * (2 * n - 1 - jj)) >> 1; }
            else {
                int o2 = ((jj + 1) * (2 * n - 2 - jj)) >> 1;
                if (o2 <= q) { jj++; off = o2; }
            }
            int kk = jj + 1 + (q - off);

            float dot = adx[jj] * adx[kk] + ady[jj] * ady[kk] + adz[jj] * adz[kk];
            float ca  = dot * ainv[jj] * ainv[kk];
            float sa  = sqrtf(fmaxf(1.0f - ca * ca, 0.0f));
            float dm  = adh[jj] + adh[kk];
            float fcj2 = afcs[jj] * afcs[kk];

            int s1 = asp[jj], s2 = asp[kk];
            int lo = min(s1, s2), hi = max(s1, s2);
            int pidx = ((lo * (2 * NSPEC + 1 - lo)) >> 1) + (hi - lo);
            float* a0 = &acc[RAD_LEN + pidx * ANG_SUB];

            float f2r[4];
            #pragma unroll
            for (int ai = 0; ai < 4; ai++) {
                float t = dm - shA[(ai + ar) & 3];
                f2r[ai] = __expf(-etaA * t * t) * fcj2;
            }

            #pragma unroll
            for (int zi = 0; zi < 4; zi++) {
                int z = zh + ((zi + zo) & 3);
                float c = ca * czv[z] + sa * szv[z];
                float x = 0.5f + 0.5f * c;
                float f1;
                if (z32) {
                    float x2 = x * x, x4 = x2 * x2, x8 = x4 * x4, x16 = x8 * x8;
                    f1 = x16 * x16;
                } else {
                    f1 = __powf(x, zeta);
                }
                #pragma unroll
                for (int ai = 0; ai < 4; ai++) {
                    int a = (ai + ar) & 3;
                    atomicAdd(&a0[a * 8 + z], f1 * f2r[ai]);
                }
            }
        }
    }
    __syncthreads();

    // ---- coalesced output ----
    float* o = out + (size_t)blockIdx.x * AEV_LEN;
    o[tid] = acc[tid];
    o[tid + 128] = acc[tid + 128];
    o[tid + 256] = acc[tid + 256];
}

extern "C" void kernel_launch(void* const* d_in, const int* in_sizes, int n_in,
                              void* d_out, int out_size) {
    const float* coords = (const float*)d_in[0];
    const float* EtaR   = (const float*)d_in[1];
    const float* ShfR   = (const float*)d_in[2];
    const float* EtaA   = (const float*)d_in[3];
    const float* Zeta   = (const float*)d_in[4];
    const float* ShfA   = (const float*)d_in[5];
    const float* ShfZ   = (const float*)d_in[6];
    const int*   spec   = (const int*)d_in[7];
    float* out = (float*)d_out;

    int M = in_sizes[0] / (ATOMS_N * 3);
    aev_kernel<<<M * ATOMS_N, 128>>>(coords, EtaR, ShfR, EtaA, Zeta, ShfA, ShfZ, spec, out);
}

// round 10
// speedup vs baseline: 1.0367x; 1.0367x over previous
#include <cuda_runtime.h>
#include <cuda_bf16.h>
#include <math.h>

#define ATOMS_N 48
#define NSPEC 4
#define RAD_LEN 64
#define ANG_SUB 32
#define ANG_LEN 320
#define AEV_LEN 384
#define RCR_F 5.2f
#define RCA_F 3.5f
#define PI_F 3.14159265358979323846f
#define SQRT095_F 0.974679434f   /* sqrt(0.95) */
#define SQRT2_F   1.414213562f

__global__ __launch_bounds__(128, 11)
void aev_kernel(const float* __restrict__ coords,
                const float* __restrict__ EtaR,
                const float* __restrict__ ShfR,
                const float* __restrict__ EtaA,
                const float* __restrict__ Zeta,
                const float* __restrict__ ShfA,
                const float* __restrict__ ShfZ,
                const int*   __restrict__ species,
                float* __restrict__ out)
{
    __shared__ float  sc[ATOMS_N * 3];
    __shared__ float4 rpack[ATOMS_N];   // (d, fcR*mask, spec_bits, -)
    __shared__ float4 apack[ATOMS_N];   // (dx, dy, dz, d/2)
    __shared__ float4 bpack[ATOMS_N];   // (ainv, sqrt2*fcA, spec_bits, -)
    __shared__ int    ncnt;
    __shared__ float  acc[AEV_LEN];
    __shared__ float  shR[16], shA[4], czv[8], szv[8];
    __shared__ float  sP[3]; // etaR, etaA, zeta

    const int tid = threadIdx.x;
    const int m  = blockIdx.x / ATOMS_N;
    const int ci = blockIdx.x % ATOMS_N;

    // ---- coalesced loads + params + zero accumulator ----
    sc[tid] = coords[m * 144 + tid];
    if (tid < 16) sc[128 + tid] = coords[m * 144 + 128 + tid];
    int myspec = 0;
    if (tid < ATOMS_N) myspec = species[m * ATOMS_N + tid];
    if (tid >= 64 && tid < 80) shR[tid - 64] = ShfR[tid - 64];
    if (tid >= 80 && tid < 84) shA[tid - 80] = ShfA[tid - 80];
    if (tid >= 88 && tid < 96) {
        float v = ShfZ[tid - 88];
        czv[tid - 88] = cosf(v);
        szv[tid - 88] = sinf(v);
    }
    if (tid == 96) sP[0] = EtaR[0];
    if (tid == 97) sP[1] = EtaA[0];
    if (tid == 98) sP[2] = Zeta[0];
    if (tid == 99) ncnt = 0;
    acc[tid] = 0.0f; acc[tid + 128] = 0.0f; acc[tid + 256] = 0.0f;
    __syncthreads();

    // ---- parallel geometry: one atom per thread + atomic compaction ----
    if (tid < ATOMS_N) {
        const float cx = sc[3 * ci], cy = sc[3 * ci + 1], cz = sc[3 * ci + 2];
        float dx = sc[3 * tid]     - cx;
        float dy = sc[3 * tid + 1] - cy;
        float dz = sc[3 * tid + 2] - cz;
        float d  = sqrtf(dx * dx + dy * dy + dz * dz);

        bool own = (tid != ci);
        float fr = (own && d <= RCR_F) ? (0.5f * __cosf(d * (PI_F / RCR_F)) + 0.5f) : 0.0f;
        rpack[tid] = make_float4(d, fr, __int_as_float(myspec), 0.0f);

        if (own && d <= RCA_F) {
            float fa = 0.5f * __cosf(d * (PI_F / RCA_F)) + 0.5f;
            int p = atomicAdd(&ncnt, 1);
            apack[p] = make_float4(dx, dy, dz, 0.5f * d);
            bpack[p] = make_float4(SQRT095_F * __frcp_rn(fmaxf(d, 1e-8f)),
                                   SQRT2_F * fa,
                                   __int_as_float(myspec), 0.0f);
        }
    }
    __syncthreads();

    // ---- radial: atom-centric, 1 LDS.128 per atom, mask folded into fcR ----
    // Writes acc[0..64); angular writes acc[64..384) — disjoint, no barrier.
    {
        const int r  = tid & 15;
        const int j0 = tid >> 4;
        const float er = sP[0];
        const float sh = shR[r];
        #pragma unroll
        for (int i = 0; i < 6; i++) {
            int j = j0 + (i << 3);
            float4 rp = rpack[j];
            float t = rp.x - sh;
            float e = 0.25f * __expf(-er * t * t) * rp.y;
            if (rp.y != 0.0f)
                atomicAdd(&acc[(__float_as_int(rp.z) << 4) + r], e);
        }
    }

    // ---- angular: 2 threads per pair (z-halves), float4 loads ----
    {
        const int lane = tid & 31;
        const int zh   = (lane & 1) << 2;   // z-half base: 0 or 4
        const int zo   = (lane >> 1) & 3;   // z rotation within half
        const int ar   = (lane >> 3) & 3;   // a rotation

        const float etaA = sP[1];
        const float zeta = sP[2];
        const bool  z32  = (zeta == 32.0f);

        const int n     = ncnt;
        const int npair = (n * (n - 1)) >> 1;
        const float fn  = (float)(2 * n - 1);

        for (int q = (tid >> 1); q < npair; q += 64) {
            // closed-form upper-triangular decode with one-step fixup
            float disc = fn * fn - 8.0f * (float)q;
            int jj = (int)(0.5f * (fn - sqrtf(disc)));
            int off = (jj * (2 * n - 1 - jj)) >> 1;
            if (off > q) { jj--; off = (jj * (2 * n - 1 - jj)) >> 1; }
            else {
                int o2 = ((jj + 1) * (2 * n - 2 - jj)) >> 1;
                if (o2 <= q) { jj++; off = o2; }
            }
            int kk = jj + 1 + (q - off);

            float4 aj = apack[jj], ak = apack[kk];
            float4 bj = bpack[jj], bk = bpack[kk];

            float dot = aj.x * ak.x + aj.y * ak.y + aj.z * ak.z;
            float ca  = dot * bj.x * bk.x;
            float sa  = sqrtf(fmaxf(1.0f - ca * ca, 0.0f));
            float dm  = aj.w + ak.w;
            float fcj2 = bj.y * bk.y;

            int s1 = __float_as_int(bj.z), s2 = __float_as_int(bk.z);
            int lo = min(s1, s2), hi = max(s1, s2);
            int pidx = ((lo * (2 * NSPEC + 1 - lo)) >> 1) + (hi - lo);
            float* a0 = &acc[RAD_LEN + pidx * ANG_SUB];

            float f2r[4];
            #pragma unroll
            for (int ai = 0; ai < 4; ai++) {
                float t = dm - shA[(ai + ar) & 3];
                f2r[ai] = __expf(-etaA * t * t) * fcj2;
            }

            #pragma unroll
            for (int zi = 0; zi < 4; zi++) {
                int z = zh + ((zi + zo) & 3);
                float c = ca * czv[z] + sa * szv[z];
                float x = 0.5f + 0.5f * c;
                float f1;
                if (z32) {
                    float x2 = x * x, x4 = x2 * x2, x8 = x4 * x4, x16 = x8 * x8;
                    f1 = x16 * x16;
                } else {
                    f1 = __powf(x, zeta);
                }
                #pragma unroll
                for (int ai = 0; ai < 4; ai++) {
                    int a = (ai + ar) & 3;
                    atomicAdd(&a0[a * 8 + z], f1 * f2r[ai]);
                }
            }
        }
    }
    __syncthreads();

    // ---- coalesced output ----
    float* o = out + (size_t)blockIdx.x * AEV_LEN;
    o[tid] = acc[tid];
    o[tid + 128] = acc[tid + 128];
    o[tid + 256] = acc[tid + 256];
}

extern "C" void kernel_launch(void* const* d_in, const int* in_sizes, int n_in,
                              void* d_out, int out_size) {
    const float* coords = (const float*)d_in[0];
    const float* EtaR   = (const float*)d_in[1];
    const float* ShfR   = (const float*)d_in[2];
    const float* EtaA   = (const float*)d_in[3];
    const float* Zeta   = (const float*)d_in[4];
    const float* ShfA   = (const float*)d_in[5];
    const float* ShfZ   = (const float*)d_in[6];
    const int*   spec   = (const int*)d_in[7];
    float* out = (float*)d_out;

    int M = in_sizes[0] / (ATOMS_N * 3);
    aev_kernel<<<M * ATOMS_N, 128>>>(coords, EtaR, ShfR, EtaA, Zeta, ShfA, ShfZ, spec, out);
}

// round 11
// speedup vs baseline: 1.0667x; 1.0289x over previous
#include <cuda_runtime.h>
#include <cuda_bf16.h>
#include <math.h>

#define ATOMS_N 48
#define NSPEC 4
#define RAD_LEN 64
#define ANG_SUB 32
#define ANG_LEN 320
#define AEV_LEN 384
#define RCR_F 5.2f
#define RCA_F 3.5f
#define PI_F 3.14159265358979323846f
#define SQRT095_F 0.974679434f   /* sqrt(0.95) */
#define SQRT2_F   1.414213562f

__global__ __launch_bounds__(128, 11)
void aev_kernel(const float* __restrict__ coords,
                const float* __restrict__ EtaR,
                const float* __restrict__ ShfR,
                const float* __restrict__ EtaA,
                const float* __restrict__ Zeta,
                const float* __restrict__ ShfA,
                const float* __restrict__ ShfZ,
                const int*   __restrict__ species,
                float* __restrict__ out)
{
    __shared__ __align__(16) float sc[ATOMS_N * 3];
    __shared__ float4 rpack[ATOMS_N];   // (d, fcR*mask, spec_bits, -)
    __shared__ float4 apack[ATOMS_N];   // (dx, dy, dz, d/2)
    __shared__ float4 bpack[ATOMS_N];   // (ainv, sqrt2*fcA, spec_bits, -)
    __shared__ int    ncnt;
    __shared__ __align__(16) float acc[AEV_LEN];
    __shared__ float  shR[16], shA[4], czv[8], szv[8];
    __shared__ float  sP[3]; // etaR, etaA, zeta

    const int tid = threadIdx.x;
    const int m  = blockIdx.x / ATOMS_N;
    const int ci = blockIdx.x % ATOMS_N;

    // ---- coalesced loads (float4) + params + zero accumulator ----
    if (tid < 36)
        reinterpret_cast<float4*>(sc)[tid] =
            reinterpret_cast<const float4*>(coords + m * 144)[tid];
    int myspec = 0;
    if (tid < ATOMS_N) myspec = species[m * ATOMS_N + tid];
    if (tid >= 64 && tid < 80) shR[tid - 64] = ShfR[tid - 64];
    if (tid >= 80 && tid < 84) shA[tid - 80] = ShfA[tid - 80];
    if (tid >= 88 && tid < 96) {
        float v = ShfZ[tid - 88];
        czv[tid - 88] = cosf(v);
        szv[tid - 88] = sinf(v);
    }
    if (tid == 96) sP[0] = EtaR[0];
    if (tid == 97) sP[1] = EtaA[0];
    if (tid == 98) sP[2] = Zeta[0];
    if (tid == 99) ncnt = 0;
    acc[tid] = 0.0f; acc[tid + 128] = 0.0f; acc[tid + 256] = 0.0f;
    __syncthreads();

    // ---- parallel geometry: one atom per thread + atomic compaction ----
    if (tid < ATOMS_N) {
        const float cx = sc[3 * ci], cy = sc[3 * ci + 1], cz = sc[3 * ci + 2];
        float dx = sc[3 * tid]     - cx;
        float dy = sc[3 * tid + 1] - cy;
        float dz = sc[3 * tid + 2] - cz;
        float d  = sqrtf(dx * dx + dy * dy + dz * dz);

        bool own = (tid != ci);
        float fr = (own && d <= RCR_F) ? (0.5f * __cosf(d * (PI_F / RCR_F)) + 0.5f) : 0.0f;
        rpack[tid] = make_float4(d, fr, __int_as_float(myspec), 0.0f);

        if (own && d <= RCA_F) {
            float fa = 0.5f * __cosf(d * (PI_F / RCA_F)) + 0.5f;
            int p = atomicAdd(&ncnt, 1);
            apack[p] = make_float4(dx, dy, dz, 0.5f * d);
            bpack[p] = make_float4(SQRT095_F * __frcp_rn(fmaxf(d, 1e-8f)),
                                   SQRT2_F * fa,
                                   __int_as_float(myspec), 0.0f);
        }
    }
    __syncthreads();

    // ---- radial: atom-centric, 1 LDS.128 per atom, mask folded into fcR ----
    // Writes acc[0..64); angular writes acc[64..384) — disjoint, no barrier.
    {
        const int r  = tid & 15;
        const int j0 = tid >> 4;
        const float er = sP[0];
        const float sh = shR[r];
        #pragma unroll
        for (int i = 0; i < 6; i++) {
            int j = j0 + (i << 3);
            float4 rp = rpack[j];
            float t = rp.x - sh;
            float e = 0.25f * __expf(-er * t * t) * rp.y;
            if (rp.y != 0.0f)
                atomicAdd(&acc[(__float_as_int(rp.z) << 4) + r], e);
        }
    }

    // ---- angular: 2 threads per pair (z-halves), hoisted constants ----
    {
        const int lane = tid & 31;
        const int zh   = (lane & 1) << 2;   // z-half base: 0 or 4
        const int zo   = (lane >> 1) & 3;   // z rotation within half
        const int ar   = (lane >> 3) & 3;   // a rotation

        // Hoist all loop-invariant shared loads into registers: the shared
        // atomicAdds below prevent the compiler from hoisting these itself
        // (it can't prove acc[] doesn't alias czv/szv/shA).
        int   zvr[4], avr[4];
        float czr[4], szr[4], shar[4];
        #pragma unroll
        for (int zi = 0; zi < 4; zi++) {
            int z = zh + ((zi + zo) & 3);
            zvr[zi] = z;
            czr[zi] = czv[z];
            szr[zi] = szv[z];
        }
        #pragma unroll
        for (int ai = 0; ai < 4; ai++) {
            int a = (ai + ar) & 3;
            avr[ai] = a << 3;
            shar[ai] = shA[a];
        }

        const float etaA = sP[1];
        const float zeta = sP[2];
        const bool  z32  = (zeta == 32.0f);

        const int n     = ncnt;
        const int npair = (n * (n - 1)) >> 1;
        const float fn  = (float)(2 * n - 1);

        for (int q = (tid >> 1); q < npair; q += 64) {
            // closed-form upper-triangular decode with one-step fixup
            float disc = fn * fn - 8.0f * (float)q;
            int jj = (int)(0.5f * (fn - sqrtf(disc)));
            int off = (jj * (2 * n - 1 - jj)) >> 1;
            if (off > q) { jj--; off = (jj * (2 * n - 1 - jj)) >> 1; }
            else {
                int o2 = ((jj + 1) * (2 * n - 2 - jj)) >> 1;
                if (o2 <= q) { jj++; off = o2; }
            }
            int kk = jj + 1 + (q - off);

            float4 aj = apack[jj], ak = apack[kk];
            float4 bj = bpack[jj], bk = bpack[kk];

            float dot = aj.x * ak.x + aj.y * ak.y + aj.z * ak.z;
            float ca  = dot * bj.x * bk.x;
            float sa  = sqrtf(fmaxf(1.0f - ca * ca, 0.0f));
            float dm  = aj.w + ak.w;
            float fcj2 = bj.y * bk.y;

            int s1 = __float_as_int(bj.z), s2 = __float_as_int(bk.z);
            int lo = min(s1, s2), hi = max(s1, s2);
            int pidx = ((lo * (2 * NSPEC + 1 - lo)) >> 1) + (hi - lo);
            float* a0 = &acc[RAD_LEN + pidx * ANG_SUB];

            float f2r[4];
            #pragma unroll
            for (int ai = 0; ai < 4; ai++) {
                float t = dm - shar[ai];
                f2r[ai] = __expf(-etaA * t * t) * fcj2;
            }

            #pragma unroll
            for (int zi = 0; zi < 4; zi++) {
                float c = ca * czr[zi] + sa * szr[zi];
                float x = 0.5f + 0.5f * c;
                float f1;
                if (z32) {
                    float x2 = x * x, x4 = x2 * x2, x8 = x4 * x4, x16 = x8 * x8;
                    f1 = x16 * x16;
                } else {
                    f1 = __powf(x, zeta);
                }
                #pragma unroll
                for (int ai = 0; ai < 4; ai++) {
                    atomicAdd(&a0[avr[ai] + zvr[zi]], f1 * f2r[ai]);
                }
            }
        }
    }
    __syncthreads();

    // ---- coalesced output (float4) ----
    float* o = out + (size_t)blockIdx.x * AEV_LEN;
    if (tid < 96)
        reinterpret_cast<float4*>(o)[tid] =
            reinterpret_cast<const float4*>(acc)[tid];
}

extern "C" void kernel_launch(void* const* d_in, const int* in_sizes, int n_in,
                              void* d_out, int out_size) {
    const float* coords = (const float*)d_in[0];
    const float* EtaR   = (const float*)d_in[1];
    const float* ShfR   = (const float*)d_in[2];
    const float* EtaA   = (const float*)d_in[3];
    const float* Zeta   = (const float*)d_in[4];
    const float* ShfA   = (const float*)d_in[5];
    const float* ShfZ   = (const float*)d_in[6];
    const int*   spec   = (const int*)d_in[7];
    float* out = (float*)d_out;

    int M = in_sizes[0] / (ATOMS_N * 3);
    aev_kernel<<<M * ATOMS_N, 128>>>(coords, EtaR, ShfR, EtaA, Zeta, ShfA, ShfZ, spec, out);
}